// round 11
// baseline (speedup 1.0000x reference)
#include <cuda_runtime.h>
#include <math.h>
#include <stdint.h>

// Problem constants
#define BB   8
#define TT   512
#define DD   128
#define DLL  16
#define KK   8
#define HTH  32
#define NROWS (BB*TT)   // 4096
#define EPS2 0.0001f

// gelu Taylor: gelu(x) = 0.5x + C0 x^2 + C1 x^4 (|x| small)
#define C0g  0.3989422804014327f
#define C1g  (-0.06649038006690545f)

// Phi LUT: 2048 entries over dl2 in [0,16), step 1/128
#define LUTN   2048
#define LUTSCL 128.0f

// Scratch
__device__ __align__(16) float  g_l[2][NROWS*DLL];   // projected l vectors (tf32-rounded)
__device__ __align__(16) float  g_PQ[2][NROWS*HTH];  // theta rank-1 vectors (tf32-rounded)
__device__ float  g_hn[2][NROWS];
__device__ float  g_ln[2][NROWS];
__device__ float  g_c[2][NROWS];
__device__ __align__(16) float2 g_lut[LUTN];

// ---------------------------------------------------------------------------
// helpers
// ---------------------------------------------------------------------------
__device__ __forceinline__ float tf32r(float x) {
    unsigned u;
    asm("cvt.rna.tf32.f32 %0, %1;" : "=r"(u) : "f"(x));
    return __uint_as_float(u);
}

// m16n8k8 tf32 MMA, fp32 accumulate (sm_80 PTX -> Blackwell HMMA)
__device__ __forceinline__ void mma8(float* d, const unsigned* a, const unsigned* b) {
    asm volatile(
        "mma.sync.aligned.m16n8k8.row.col.f32.tf32.tf32.f32 "
        "{%0,%1,%2,%3},{%4,%5,%6,%7},{%8,%9},{%0,%1,%2,%3};"
        : "+f"(d[0]), "+f"(d[1]), "+f"(d[2]), "+f"(d[3])
        : "r"(a[0]), "r"(a[1]), "r"(a[2]), "r"(a[3]), "r"(b[0]), "r"(b[1]));
}

__device__ __forceinline__ unsigned ldsu(const float* p) {
    return __float_as_uint(*p);
}

__device__ __forceinline__ float gelu_exact(float x) {
    return 0.5f * x * (1.0f + erff(x * 0.7071067811865475f));
}

// ---------------------------------------------------------------------------
// prep: grid (64, 3), block 128, dynamic smem.  (unchanged from R10)
// ---------------------------------------------------------------------------
#define P_SROW 0                       // 64 x 132
#define P_SWT  (P_SROW + 64*132)       // 24 x 132 (transposed weights)
#define P_SL   (P_SWT  + 24*132)       // 64 x 20
#define P_STH  (P_SL   + 64*20)        // 64 x 12
#define P_SCW  (P_STH  + 64*12)        // 8 x 32
#define PREP_SMEM ((P_SCW + 256) * 4)

__global__ __launch_bounds__(128)
void prep_kernel(const float* __restrict__ h,
                 const float* __restrict__ hsrc,
                 const float* __restrict__ W_l,
                 const float* __restrict__ W_theta,
                 const float* __restrict__ wq,
                 const float* __restrict__ ws,
                 const float* __restrict__ wd,
                 const float* __restrict__ b1,
                 const float* __restrict__ w2_w,
                 const float* __restrict__ phi1_w,
                 const float* __restrict__ phi1_b,
                 const float* __restrict__ phi2_w,
                 const float* __restrict__ phi2_b)
{
    int side = blockIdx.y;
    int tid  = threadIdx.x;

    if (side == 2) {
        int wid = tid >> 5, lane = tid & 31;
        float w = phi1_w[lane], b = phi1_b[lane], v = phi2_w[lane];
        float ph2b = phi2_b[0];
        #pragma unroll
        for (int sub = 0; sub < 8; sub++) {
            int e = blockIdx.x * 32 + wid * 8 + sub;
            float x0 = (float)e       * (1.0f / LUTSCL);
            float x1 = (float)(e + 1) * (1.0f / LUTSCL);
            float s0 = gelu_exact(fmaf(x0, w, b)) * v;
            float s1 = gelu_exact(fmaf(x1, w, b)) * v;
            #pragma unroll
            for (int o = 16; o > 0; o >>= 1) {
                s0 += __shfl_xor_sync(0xffffffffu, s0, o);
                s1 += __shfl_xor_sync(0xffffffffu, s1, o);
            }
            if (lane == 0) {
                float a0 = s0 + ph2b, a1 = s1 + ph2b;
                float c0 = fmaxf(a0, 0.f) + log1pf(expf(-fabsf(a0)));
                float c1 = fmaxf(a1, 0.f) + log1pf(expf(-fabsf(a1)));
                float p0 = expf(-c0 * x0);
                float p1 = expf(-c1 * x1);
                g_lut[e] = make_float2(p0, p1 - p0);
            }
        }
        return;
    }

    extern __shared__ float ps[];
    float* SROW = ps + P_SROW;
    float* SWT  = ps + P_SWT;
    float* SL   = ps + P_SL;
    float* STH  = ps + P_STH;
    float* SCW  = ps + P_SCW;

    int r0 = blockIdx.x * 64;
    const float* src = (side == 0) ? h : hsrc;

    {
        const float4* sv = (const float4*)(src + (size_t)r0 * DD);
        #pragma unroll
        for (int i = 0; i < 16; i++) {
            int idx = tid + i * 128;
            int r = idx >> 5, c4 = idx & 31;
            *(float4*)(SROW + r * 132 + c4 * 4) = sv[r * 32 + c4];
        }
        #pragma unroll
        for (int i = 0; i < 16; i++) {
            int idx = tid + i * 128;
            int c = idx & 15, d = idx >> 4;
            SWT[c * 132 + d] = W_l[d * DLL + c];
        }
        #pragma unroll
        for (int i = 0; i < 8; i++) {
            int idx = tid + i * 128;
            int c = idx & 7, d = idx >> 3;
            SWT[(16 + c) * 132 + d] = W_theta[d * KK + c];
        }
        #pragma unroll
        for (int i = 0; i < 2; i++) {
            int idx = tid + i * 128;
            float a = wq[idx], s = ws[idx], d = wd[idx];
            SCW[idx] = (side == 0) ? (a + d) : (s - d);
        }
    }
    __syncthreads();

    {
        int rg = tid >> 3, cg = tid & 7;
        float acc[4][3];
        #pragma unroll
        for (int i = 0; i < 4; i++)
            #pragma unroll
            for (int j = 0; j < 3; j++) acc[i][j] = 0.f;

        const float* sr = SROW + (rg * 4) * 132;
        #pragma unroll 4
        for (int kc = 0; kc < 32; kc++) {
            float4 x[4], w[3];
            #pragma unroll
            for (int i = 0; i < 4; i++)
                x[i] = *(const float4*)(sr + i * 132 + kc * 4);
            #pragma unroll
            for (int j = 0; j < 3; j++)
                w[j] = *(const float4*)(SWT + (cg + 8 * j) * 132 + kc * 4);
            #pragma unroll
            for (int i = 0; i < 4; i++)
                #pragma unroll
                for (int j = 0; j < 3; j++) {
                    acc[i][j] = fmaf(x[i].x, w[j].x, acc[i][j]);
                    acc[i][j] = fmaf(x[i].y, w[j].y, acc[i][j]);
                    acc[i][j] = fmaf(x[i].z, w[j].z, acc[i][j]);
                    acc[i][j] = fmaf(x[i].w, w[j].w, acc[i][j]);
                }
        }
        #pragma unroll
        for (int i = 0; i < 4; i++)
            #pragma unroll
            for (int j = 0; j < 3; j++) {
                int r = rg * 4 + i, c = cg + 8 * j;
                if (c < DLL) {
                    float lr = tf32r(acc[i][j]);
                    SL[r * 20 + c] = lr;
                    g_l[side][(size_t)(r0 + r) * DLL + c] = lr;
                } else {
                    STH[r * 12 + (c - 16)] = acc[i][j];
                }
            }
    }
    __syncthreads();

    {
        int r = tid >> 1, half = tid & 1;
        const float* sr = SROW + r * 132 + half * 64;
        float a = 0.f;
        #pragma unroll
        for (int c4 = 0; c4 < 16; c4++) {
            float4 x = *(const float4*)(sr + c4 * 4);
            float x0 = tf32r(x.x), x1 = tf32r(x.y);
            float x2 = tf32r(x.z), x3 = tf32r(x.w);
            a = fmaf(x0, x0, a); a = fmaf(x1, x1, a);
            a = fmaf(x2, x2, a); a = fmaf(x3, x3, a);
        }
        a += __shfl_xor_sync(0xffffffffu, a, 1);
        if (half == 0) g_hn[side][r0 + r] = a;
    }
    if (tid < 64) {
        const float* sr = SL + tid * 20;
        float a = 0.f;
        #pragma unroll
        for (int c4 = 0; c4 < 4; c4++) {
            float4 x = *(const float4*)(sr + c4 * 4);
            a = fmaf(x.x, x.x, a); a = fmaf(x.y, x.y, a);
            a = fmaf(x.z, x.z, a); a = fmaf(x.w, x.w, a);
        }
        g_ln[side][r0 + tid] = a;
    }

    #pragma unroll
    for (int i = 0; i < 16; i++) {
        int idx = tid + i * 128;
        int r = idx >> 5, c = idx & 31;
        float x = (side == 0) ? __ldg(&b1[c]) : 0.f;
        #pragma unroll
        for (int k = 0; k < KK; k++)
            x = fmaf(STH[r * 12 + k], SCW[k * HTH + c], x);
        float w2 = __ldg(&w2_w[c]);
        float x2 = x * x;
        g_PQ[side][(size_t)(r0 + r) * HTH + c] =
            tf32r((side == 0) ? (2.0f * C0g * w2 * x) : x);
        float v = w2 * (fmaf(C1g, x2 * x2, fmaf(C0g, x2, 0.5f * x)));
        #pragma unroll
        for (int o = 16; o > 0; o >>= 1)
            v += __shfl_xor_sync(0xffffffffu, v, o);
        if (c == 0) g_c[side][r0 + r] = v;
    }
}

// ---------------------------------------------------------------------------
// main: 128x128 tile, 512 threads (16 warps); warp = 16 rows x 64 cols.
// m16n8k8 tf32 mma for all three Grams.
// ---------------------------------------------------------------------------
// float offsets in dynamic smem
#define S_HT  0                        // 128 x 132
#define S_HS  (S_HT  + 128*132)
#define S_PT  (S_HS  + 128*132)        // 128 x 36
#define S_QS  (S_PT  + 128*36)
#define S_LT  (S_QS  + 128*36)         // 128 x 20
#define S_LS  (S_LT  + 128*20)
#define S_LUT (S_LS  + 128*20)         // 2048 float2
#define S_SC  (S_LUT + 4096)           // 768
#define MAIN_SMEM ((S_SC + 768) * 4)

__global__ __launch_bounds__(512)
void main_kernel(const float* __restrict__ h, const float* __restrict__ hsrc,
                 const float* __restrict__ w2_b, float* __restrict__ out)
{
    extern __shared__ float S[];
    float* sc = S + S_SC;
    // sc: [0]=hn_t [128]=hn_s [256]=ln_t [384]=ln_s [512]=c_t [640]=c_s

    int bz  = blockIdx.z;
    int t0  = blockIdx.y * 128;
    int s0  = blockIdx.x * 128;
    int tid = threadIdx.x;
    int rt  = bz * TT + t0;
    int rs  = bz * TT + s0;

    // ================= stage =================
    {
        const float4* tv = (const float4*)(h    + (size_t)rt * DD);
        const float4* sv = (const float4*)(hsrc + (size_t)rs * DD);
        #pragma unroll
        for (int i = 0; i < 8; i++) {
            int idx = tid + i * 512;        // < 4096
            int r = idx >> 5, c4 = idx & 31;
            float4 a = tv[r * 32 + c4];
            a.x = tf32r(a.x); a.y = tf32r(a.y); a.z = tf32r(a.z); a.w = tf32r(a.w);
            *(float4*)(S + S_HT + r * 132 + c4 * 4) = a;
            float4 b = sv[r * 32 + c4];
            b.x = tf32r(b.x); b.y = tf32r(b.y); b.z = tf32r(b.z); b.w = tf32r(b.w);
            *(float4*)(S + S_HS + r * 132 + c4 * 4) = b;
        }
        const float4* pt = (const float4*)(g_PQ[0] + (size_t)rt * HTH);
        const float4* qs = (const float4*)(g_PQ[1] + (size_t)rs * HTH);
        #pragma unroll
        for (int i = 0; i < 2; i++) {
            int idx = tid + i * 512;        // < 1024
            int r = idx >> 3, c4 = idx & 7;
            *(float4*)(S + S_PT + r * 36 + c4 * 4) = pt[r * 8 + c4];
            *(float4*)(S + S_QS + r * 36 + c4 * 4) = qs[r * 8 + c4];
        }
        if (tid < 512) {
            int r = tid >> 2, c4 = tid & 3;
            const float4* lt = (const float4*)(g_l[0] + (size_t)rt * DLL);
            const float4* ls = (const float4*)(g_l[1] + (size_t)rs * DLL);
            *(float4*)(S + S_LT + r * 20 + c4 * 4) = lt[r * 4 + c4];
            *(float4*)(S + S_LS + r * 20 + c4 * 4) = ls[r * 4 + c4];
        }
        const float4* lv = (const float4*)g_lut;
        #pragma unroll
        for (int i = 0; i < 2; i++) {
            int idx = tid + i * 512;        // < 1024
            *(float4*)(S + S_LUT + idx * 4) = lv[idx];
        }
        if (tid < 128) {
            sc[tid]       = g_hn[0][rt + tid];
            sc[128 + tid] = g_hn[1][rs + tid];
            sc[256 + tid] = g_ln[0][rt + tid];
            sc[384 + tid] = g_ln[1][rs + tid];
            sc[512 + tid] = g_c [0][rt + tid];
            sc[640 + tid] = g_c [1][rs + tid];
        }
    }
    float w2b = __ldg(w2_b);
    __syncthreads();

    int wid  = tid >> 5;        // 0..15
    int lane = tid & 31;
    int g    = lane >> 2;       // 0..7
    int q    = lane & 3;        // 0..3
    int m0   = (wid & 7) * 16;  // warp rows [m0, m0+16)
    int nh   = wid >> 3;        // n-half: n-tiles [nh*8, nh*8+8)

    // per-thread row scalars
    float ct0  = sc[512 + m0 + g],  ct1  = sc[512 + m0 + g + 8];
    float lnt0 = sc[256 + m0 + g],  lnt1 = sc[256 + m0 + g + 8];
    float hnt0 = sc[m0 + g],        hnt1 = sc[m0 + g + 8];

    // ============ Phase A: theta + l Grams -> tp[8][4] ============
    unsigned aT[4][4], aL[2][4];
    #pragma unroll
    for (int ks = 0; ks < 4; ks++) {
        const float* p0 = S + S_PT + (m0 + g) * 36 + ks * 8 + q;
        const float* p1 = S + S_PT + (m0 + g + 8) * 36 + ks * 8 + q;
        aT[ks][0] = ldsu(p0);     aT[ks][1] = ldsu(p1);
        aT[ks][2] = ldsu(p0 + 4); aT[ks][3] = ldsu(p1 + 4);
    }
    #pragma unroll
    for (int ks = 0; ks < 2; ks++) {
        const float* p0 = S + S_LT + (m0 + g) * 20 + ks * 8 + q;
        const float* p1 = S + S_LT + (m0 + g + 8) * 20 + ks * 8 + q;
        aL[ks][0] = ldsu(p0);     aL[ks][1] = ldsu(p1);
        aL[ks][2] = ldsu(p0 + 4); aL[ks][3] = ldsu(p1 + 4);
    }

    float tp[8][4];
    const float2* slut = (const float2*)(S + S_LUT);

    #pragma unroll
    for (int n = 0; n < 8; n++) {
        int n0 = (nh * 8 + n) * 8;
        float dT[4] = {0.f, 0.f, 0.f, 0.f};
        #pragma unroll
        for (int ks = 0; ks < 4; ks++) {
            const float* bp = S + S_QS + (n0 + g) * 36 + ks * 8 + q;
            unsigned b[2] = { ldsu(bp), ldsu(bp + 4) };
            mma8(dT, aT[ks], b);
        }
        float dL[4] = {0.f, 0.f, 0.f, 0.f};
        #pragma unroll
        for (int ks = 0; ks < 2; ks++) {
            const float* bp = S + S_LS + (n0 + g) * 20 + ks * 8 + q;
            unsigned b[2] = { ldsu(bp), ldsu(bp + 4) };
            mma8(dL, aL[ks], b);
        }
        int c0 = n0 + 2 * q, c1 = c0 + 1;
        float cs0  = sc[640 + c0], cs1  = sc[640 + c1];
        float lns0 = sc[384 + c0], lns1 = sc[384 + c1];
        float ctv[4]  = { ct0, ct0, ct1, ct1 };
        float csv[4]  = { cs0, cs1, cs0, cs1 };
        float lntv[4] = { lnt0, lnt0, lnt1, lnt1 };
        float lnsv[4] = { lns0, lns1, lns0, lns1 };
        #pragma unroll
        for (int e = 0; e < 4; e++) {
            float a = w2b + ctv[e] + csv[e] + dT[e];
            float u = a * a;
            float Th = a * fmaf(u, fmaf(u, fmaf(u, -0.05396825397f,
                                 0.13333333333f), -0.33333333333f), 1.0f);
            float dl2 = fmaxf(fmaf(-2.f, dL[e], lntv[e] + lnsv[e]), 0.f);
            float t   = fminf(dl2 * LUTSCL, (float)(LUTN - 1));
            int   ix  = (int)t;
            float fr  = t - (float)ix;
            float2 lv = slut[ix];
            tp[n][e] = -Th * fmaf(fr, lv.y, lv.x);
        }
    }

    // ============ Phase B: h Gram (K=128) ============
    float acc[8][4];
    #pragma unroll
    for (int n = 0; n < 8; n++)
        #pragma unroll
        for (int e = 0; e < 4; e++) acc[n][e] = 0.f;

    #pragma unroll 4
    for (int ks = 0; ks < 16; ks++) {
        int k0 = ks * 8;
        const float* p0 = S + S_HT + (m0 + g) * 132 + k0 + q;
        const float* p1 = S + S_HT + (m0 + g + 8) * 132 + k0 + q;
        unsigned a[4] = { ldsu(p0), ldsu(p1), ldsu(p0 + 4), ldsu(p1 + 4) };
        #pragma unroll
        for (int n = 0; n < 8; n++) {
            const float* bp = S + S_HS + ((nh * 8 + n) * 8 + g) * 132 + k0 + q;
            unsigned b[2] = { ldsu(bp), ldsu(bp + 4) };
            mma8(acc[n], a, b);
        }
    }

    // ============ epilogue ============
    {
        size_t orow0 = ((size_t)(bz * TT + t0 + m0 + g)) * TT + s0;
        size_t orow1 = orow0 + (size_t)8 * TT;
        #pragma unroll
        for (int n = 0; n < 8; n++) {
            int c0 = (nh * 8 + n) * 8 + 2 * q;
            float hns0 = sc[128 + c0], hns1 = sc[128 + c0 + 1];
            float d0 = fmaxf(fmaf(-2.f, acc[n][0], hnt0 + hns0), 0.f) + EPS2;
            float d1 = fmaxf(fmaf(-2.f, acc[n][1], hnt0 + hns1), 0.f) + EPS2;
            float d2 = fmaxf(fmaf(-2.f, acc[n][2], hnt1 + hns0), 0.f) + EPS2;
            float d3 = fmaxf(fmaf(-2.f, acc[n][3], hnt1 + hns1), 0.f) + EPS2;
            float2 v0 = make_float2(tp[n][0] * rsqrtf(d0), tp[n][1] * rsqrtf(d1));
            float2 v1 = make_float2(tp[n][2] * rsqrtf(d2), tp[n][3] * rsqrtf(d3));
            *(float2*)(out + orow0 + c0) = v0;
            *(float2*)(out + orow1 + c0) = v1;
        }
    }
}

// ---------------------------------------------------------------------------
extern "C" void kernel_launch(void* const* d_in, const int* in_sizes, int n_in,
                              void* d_out, int out_size)
{
    (void)in_sizes; (void)n_in; (void)out_size;
    const float* h       = (const float*)d_in[0];
    const float* hsrc    = (const float*)d_in[1];
    const float* W_l     = (const float*)d_in[2];
    const float* W_theta = (const float*)d_in[3];
    const float* phi1_w  = (const float*)d_in[4];
    const float* phi1_b  = (const float*)d_in[5];
    const float* phi2_w  = (const float*)d_in[6];
    const float* phi2_b  = (const float*)d_in[7];
    const float* wq      = (const float*)d_in[8];
    const float* ws      = (const float*)d_in[9];
    const float* wd      = (const float*)d_in[10];
    const float* b1      = (const float*)d_in[11];
    const float* w2_w    = (const float*)d_in[12];
    const float* w2_b    = (const float*)d_in[13];
    float* out = (float*)d_out;

    cudaFuncSetAttribute(prep_kernel,
                         cudaFuncAttributeMaxDynamicSharedMemorySize, PREP_SMEM);
    cudaFuncSetAttribute(main_kernel,
                         cudaFuncAttributeMaxDynamicSharedMemorySize, MAIN_SMEM);

    prep_kernel<<<dim3(64, 3), 128, PREP_SMEM>>>(h, hsrc, W_l, W_theta,
                                                 wq, ws, wd, b1, w2_w,
                                                 phi1_w, phi1_b, phi2_w, phi2_b);
    main_kernel<<<dim3(4, 4, BB), 512, MAIN_SMEM>>>(h, hsrc, w2_b, out);
}

// round 12
// speedup vs baseline: 1.1464x; 1.1464x over previous
#include <cuda_runtime.h>
#include <math.h>
#include <stdint.h>

// Problem constants
#define BB   8
#define TT   512
#define DD   128
#define DLL  16
#define KK   8
#define HTH  32
#define NROWS (BB*TT)   // 4096
#define EPS2 0.0001f

// gelu Taylor: gelu(x) = 0.5x + C0 x^2 + C1 x^4 (|x| small)
#define C0g  0.3989422804014327f
#define C1g  (-0.06649038006690545f)

// Phi LUT: 2048 entries over dl2 in [0,16), step 1/128
#define LUTN   2048
#define LUTSCL 128.0f

// Scratch
__device__ __align__(16) float    g_l[2][NROWS*DLL];   // l vectors (tf32-rounded)
__device__ __align__(16) float    g_PQ[2][NROWS*HTH];  // theta vectors (tf32-rounded)
__device__ __align__(16) unsigned g_hb[2][NROWS*64];   // h rows packed bf16x2
__device__ float  g_hn[2][NROWS];
__device__ float  g_ln[2][NROWS];
__device__ float  g_c[2][NROWS];
__device__ __align__(16) float2 g_lut[LUTN];

// ---------------------------------------------------------------------------
// helpers
// ---------------------------------------------------------------------------
__device__ __forceinline__ float tf32r(float x) {
    unsigned u;
    asm("cvt.rna.tf32.f32 %0, %1;" : "=r"(u) : "f"(x));
    return __uint_as_float(u);
}

__device__ __forceinline__ float bf16r(float x) {
    unsigned p;
    asm("cvt.rn.bf16x2.f32 %0, %1, %2;" : "=r"(p) : "f"(x), "f"(x));
    return __uint_as_float(p << 16);
}

__device__ __forceinline__ unsigned bf16pack(float lo, float hi) {
    unsigned p;
    asm("cvt.rn.bf16x2.f32 %0, %1, %2;" : "=r"(p) : "f"(hi), "f"(lo));
    return p;
}

// m16n8k8 tf32 MMA, fp32 accumulate
__device__ __forceinline__ void mma8(float* d, const unsigned* a, const unsigned* b) {
    asm volatile(
        "mma.sync.aligned.m16n8k8.row.col.f32.tf32.tf32.f32 "
        "{%0,%1,%2,%3},{%4,%5,%6,%7},{%8,%9},{%0,%1,%2,%3};"
        : "+f"(d[0]), "+f"(d[1]), "+f"(d[2]), "+f"(d[3])
        : "r"(a[0]), "r"(a[1]), "r"(a[2]), "r"(a[3]), "r"(b[0]), "r"(b[1]));
}

// m16n8k16 bf16 MMA, fp32 accumulate
__device__ __forceinline__ void mma16(float* d, const unsigned* a, const unsigned* b) {
    asm volatile(
        "mma.sync.aligned.m16n8k16.row.col.f32.bf16.bf16.f32 "
        "{%0,%1,%2,%3},{%4,%5,%6,%7},{%8,%9},{%0,%1,%2,%3};"
        : "+f"(d[0]), "+f"(d[1]), "+f"(d[2]), "+f"(d[3])
        : "r"(a[0]), "r"(a[1]), "r"(a[2]), "r"(a[3]), "r"(b[0]), "r"(b[1]));
}

__device__ __forceinline__ unsigned ldsu(const float* p) {
    return __float_as_uint(*p);
}

__device__ __forceinline__ unsigned smem_u32(const void* p) {
    unsigned a;
    asm("{ .reg .u64 t; cvta.to.shared.u64 t, %1; cvt.u32.u64 %0, t; }"
        : "=r"(a) : "l"(p));
    return a;
}

#define CP_ASYNC16(dst_u32, src) \
    asm volatile("cp.async.ca.shared.global [%0], [%1], 16;" \
                 :: "r"(dst_u32), "l"(src) : "memory")

__device__ __forceinline__ float gelu_exact(float x) {
    return 0.5f * x * (1.0f + erff(x * 0.7071067811865475f));
}

// ---------------------------------------------------------------------------
// prep: grid (64, 3), block 128, dynamic smem.
// Adds: bf16 copy of h rows (g_hb) and hn from bf16-rounded values.
// ---------------------------------------------------------------------------
#define P_SROW 0                       // 64 x 132
#define P_SWT  (P_SROW + 64*132)       // 24 x 132 (transposed weights)
#define P_SL   (P_SWT  + 24*132)       // 64 x 20
#define P_STH  (P_SL   + 64*20)        // 64 x 12
#define P_SCW  (P_STH  + 64*12)        // 8 x 32
#define PREP_SMEM ((P_SCW + 256) * 4)

__global__ __launch_bounds__(128)
void prep_kernel(const float* __restrict__ h,
                 const float* __restrict__ hsrc,
                 const float* __restrict__ W_l,
                 const float* __restrict__ W_theta,
                 const float* __restrict__ wq,
                 const float* __restrict__ ws,
                 const float* __restrict__ wd,
                 const float* __restrict__ b1,
                 const float* __restrict__ w2_w,
                 const float* __restrict__ phi1_w,
                 const float* __restrict__ phi1_b,
                 const float* __restrict__ phi2_w,
                 const float* __restrict__ phi2_b)
{
    int side = blockIdx.y;
    int tid  = threadIdx.x;

    if (side == 2) {
        int wid = tid >> 5, lane = tid & 31;
        float w = phi1_w[lane], b = phi1_b[lane], v = phi2_w[lane];
        float ph2b = phi2_b[0];
        #pragma unroll
        for (int sub = 0; sub < 8; sub++) {
            int e = blockIdx.x * 32 + wid * 8 + sub;
            float x0 = (float)e       * (1.0f / LUTSCL);
            float x1 = (float)(e + 1) * (1.0f / LUTSCL);
            float s0 = gelu_exact(fmaf(x0, w, b)) * v;
            float s1 = gelu_exact(fmaf(x1, w, b)) * v;
            #pragma unroll
            for (int o = 16; o > 0; o >>= 1) {
                s0 += __shfl_xor_sync(0xffffffffu, s0, o);
                s1 += __shfl_xor_sync(0xffffffffu, s1, o);
            }
            if (lane == 0) {
                float a0 = s0 + ph2b, a1 = s1 + ph2b;
                float c0 = fmaxf(a0, 0.f) + log1pf(expf(-fabsf(a0)));
                float c1 = fmaxf(a1, 0.f) + log1pf(expf(-fabsf(a1)));
                float p0 = expf(-c0 * x0);
                float p1 = expf(-c1 * x1);
                g_lut[e] = make_float2(p0, p1 - p0);
            }
        }
        return;
    }

    extern __shared__ float ps[];
    float* SROW = ps + P_SROW;
    float* SWT  = ps + P_SWT;
    float* SL   = ps + P_SL;
    float* STH  = ps + P_STH;
    float* SCW  = ps + P_SCW;

    int r0 = blockIdx.x * 64;
    const float* src = (side == 0) ? h : hsrc;

    {
        const float4* sv = (const float4*)(src + (size_t)r0 * DD);
        #pragma unroll
        for (int i = 0; i < 16; i++) {
            int idx = tid + i * 128;
            int r = idx >> 5, c4 = idx & 31;
            *(float4*)(SROW + r * 132 + c4 * 4) = sv[r * 32 + c4];
        }
        #pragma unroll
        for (int i = 0; i < 16; i++) {
            int idx = tid + i * 128;
            int c = idx & 15, d = idx >> 4;
            SWT[c * 132 + d] = W_l[d * DLL + c];
        }
        #pragma unroll
        for (int i = 0; i < 8; i++) {
            int idx = tid + i * 128;
            int c = idx & 7, d = idx >> 3;
            SWT[(16 + c) * 132 + d] = W_theta[d * KK + c];
        }
        #pragma unroll
        for (int i = 0; i < 2; i++) {
            int idx = tid + i * 128;
            float a = wq[idx], s = ws[idx], d = wd[idx];
            SCW[idx] = (side == 0) ? (a + d) : (s - d);
        }
    }
    __syncthreads();

    // bf16 copy of h rows (packed pairs), 4096 u32 per block
    #pragma unroll
    for (int i = 0; i < 32; i++) {
        int idx = tid + i * 128;
        int r = idx >> 6, j = idx & 63;
        float x0 = SROW[r * 132 + 2 * j];
        float x1 = SROW[r * 132 + 2 * j + 1];
        g_hb[side][(size_t)(r0 + r) * 64 + j] = bf16pack(x0, x1);
    }

    {
        int rg = tid >> 3, cg = tid & 7;
        float acc[4][3];
        #pragma unroll
        for (int i = 0; i < 4; i++)
            #pragma unroll
            for (int j = 0; j < 3; j++) acc[i][j] = 0.f;

        const float* sr = SROW + (rg * 4) * 132;
        #pragma unroll 4
        for (int kc = 0; kc < 32; kc++) {
            float4 x[4], w[3];
            #pragma unroll
            for (int i = 0; i < 4; i++)
                x[i] = *(const float4*)(sr + i * 132 + kc * 4);
            #pragma unroll
            for (int j = 0; j < 3; j++)
                w[j] = *(const float4*)(SWT + (cg + 8 * j) * 132 + kc * 4);
            #pragma unroll
            for (int i = 0; i < 4; i++)
                #pragma unroll
                for (int j = 0; j < 3; j++) {
                    acc[i][j] = fmaf(x[i].x, w[j].x, acc[i][j]);
                    acc[i][j] = fmaf(x[i].y, w[j].y, acc[i][j]);
                    acc[i][j] = fmaf(x[i].z, w[j].z, acc[i][j]);
                    acc[i][j] = fmaf(x[i].w, w[j].w, acc[i][j]);
                }
        }
        #pragma unroll
        for (int i = 0; i < 4; i++)
            #pragma unroll
            for (int j = 0; j < 3; j++) {
                int r = rg * 4 + i, c = cg + 8 * j;
                if (c < DLL) {
                    float lr = tf32r(acc[i][j]);
                    SL[r * 20 + c] = lr;
                    g_l[side][(size_t)(r0 + r) * DLL + c] = lr;
                } else {
                    STH[r * 12 + (c - 16)] = acc[i][j];
                }
            }
    }
    __syncthreads();

    {
        // hn from bf16-rounded h (consistent with main's Gram inputs)
        int r = tid >> 1, half = tid & 1;
        const float* sr = SROW + r * 132 + half * 64;
        float a = 0.f;
        #pragma unroll
        for (int c4 = 0; c4 < 16; c4++) {
            float4 x = *(const float4*)(sr + c4 * 4);
            float x0 = bf16r(x.x), x1 = bf16r(x.y);
            float x2 = bf16r(x.z), x3 = bf16r(x.w);
            a = fmaf(x0, x0, a); a = fmaf(x1, x1, a);
            a = fmaf(x2, x2, a); a = fmaf(x3, x3, a);
        }
        a += __shfl_xor_sync(0xffffffffu, a, 1);
        if (half == 0) g_hn[side][r0 + r] = a;
    }
    if (tid < 64) {
        const float* sr = SL + tid * 20;
        float a = 0.f;
        #pragma unroll
        for (int c4 = 0; c4 < 4; c4++) {
            float4 x = *(const float4*)(sr + c4 * 4);
            a = fmaf(x.x, x.x, a); a = fmaf(x.y, x.y, a);
            a = fmaf(x.z, x.z, a); a = fmaf(x.w, x.w, a);
        }
        g_ln[side][r0 + tid] = a;
    }

    #pragma unroll
    for (int i = 0; i < 16; i++) {
        int idx = tid + i * 128;
        int r = idx >> 5, c = idx & 31;
        float x = (side == 0) ? __ldg(&b1[c]) : 0.f;
        #pragma unroll
        for (int k = 0; k < KK; k++)
            x = fmaf(STH[r * 12 + k], SCW[k * HTH + c], x);
        float w2 = __ldg(&w2_w[c]);
        float x2 = x * x;
        g_PQ[side][(size_t)(r0 + r) * HTH + c] =
            tf32r((side == 0) ? (2.0f * C0g * w2 * x) : x);
        float v = w2 * (fmaf(C1g, x2 * x2, fmaf(C0g, x2, 0.5f * x)));
        #pragma unroll
        for (int o = 16; o > 0; o >>= 1)
            v += __shfl_xor_sync(0xffffffffu, v, o);
        if (c == 0) g_c[side][r0 + r] = v;
    }
}

// ---------------------------------------------------------------------------
// main: 128x128 tile, 512 threads (16 warps); warp = 16 rows x 64 cols.
// Phase A: theta+l via tf32 m16n8k8. Phase B: h Gram via bf16 m16n8k16,
// tiles fetched by cp.async overlapped with phase A.
// ---------------------------------------------------------------------------
// float-word offsets in dynamic smem
#define S_HBT 0                        // 128 x 68 u32 (bf16x2 rows)
#define S_HBS (S_HBT + 128*68)
#define S_PT  (S_HBS + 128*68)         // 128 x 36
#define S_QS  (S_PT  + 128*36)
#define S_LT  (S_QS  + 128*36)         // 128 x 20
#define S_LS  (S_LT  + 128*20)
#define S_LUT (S_LS  + 128*20)         // 2048 float2
#define S_SC  (S_LUT + 4096)           // 768
#define MAIN_SMEM ((S_SC + 768) * 4)

__global__ __launch_bounds__(512)
void main_kernel(const float* __restrict__ w2_b, float* __restrict__ out)
{
    extern __shared__ float S[];
    float* sc = S + S_SC;
    // sc: [0]=hn_t [128]=hn_s [256]=ln_t [384]=ln_s [512]=c_t [640]=c_s

    int bz  = blockIdx.z;
    int t0  = blockIdx.y * 128;
    int s0  = blockIdx.x * 128;
    int tid = threadIdx.x;
    int rt  = bz * TT + t0;
    int rs  = bz * TT + s0;

    // ---- cp.async the bf16 h tiles (overlaps with phase A) ----
    {
        unsigned dT = smem_u32(S + S_HBT);
        unsigned dS = smem_u32(S + S_HBS);
        const unsigned* gt = g_hb[0] + (size_t)rt * 64;
        const unsigned* gs = g_hb[1] + (size_t)rs * 64;
        #pragma unroll
        for (int i = 0; i < 4; i++) {
            int idx = tid + i * 512;        // < 2048
            int r = idx >> 4, c = idx & 15; // row, 16B chunk
            unsigned off = (unsigned)(r * 68 + c * 4) * 4u;
            CP_ASYNC16(dT + off, gt + r * 64 + c * 4);
            CP_ASYNC16(dS + off, gs + r * 64 + c * 4);
        }
        asm volatile("cp.async.commit_group;" ::: "memory");
    }

    // ---- stage phase-A tiles ----
    {
        const float4* pt = (const float4*)(g_PQ[0] + (size_t)rt * HTH);
        const float4* qs = (const float4*)(g_PQ[1] + (size_t)rs * HTH);
        #pragma unroll
        for (int i = 0; i < 2; i++) {
            int idx = tid + i * 512;        // < 1024
            int r = idx >> 3, c4 = idx & 7;
            *(float4*)(S + S_PT + r * 36 + c4 * 4) = pt[r * 8 + c4];
            *(float4*)(S + S_QS + r * 36 + c4 * 4) = qs[r * 8 + c4];
        }
        {
            int r = tid >> 2, c4 = tid & 3;
            const float4* lt = (const float4*)(g_l[0] + (size_t)rt * DLL);
            const float4* ls = (const float4*)(g_l[1] + (size_t)rs * DLL);
            *(float4*)(S + S_LT + r * 20 + c4 * 4) = lt[r * 4 + c4];
            *(float4*)(S + S_LS + r * 20 + c4 * 4) = ls[r * 4 + c4];
        }
        const float4* lv = (const float4*)g_lut;
        #pragma unroll
        for (int i = 0; i < 2; i++) {
            int idx = tid + i * 512;        // < 1024
            *(float4*)(S + S_LUT + idx * 4) = lv[idx];
        }
        if (tid < 128) {
            sc[tid]       = g_hn[0][rt + tid];
            sc[128 + tid] = g_hn[1][rs + tid];
            sc[256 + tid] = g_ln[0][rt + tid];
            sc[384 + tid] = g_ln[1][rs + tid];
            sc[512 + tid] = g_c [0][rt + tid];
            sc[640 + tid] = g_c [1][rs + tid];
        }
    }
    float w2b = __ldg(w2_b);
    __syncthreads();

    int wid  = tid >> 5;        // 0..15
    int lane = tid & 31;
    int g    = lane >> 2;       // 0..7
    int q    = lane & 3;        // 0..3
    int m0   = (wid & 7) * 16;  // warp rows [m0, m0+16)
    int nh   = wid >> 3;        // n-half: n-tiles [nh*8, nh*8+8)

    float ct0  = sc[512 + m0 + g],  ct1  = sc[512 + m0 + g + 8];
    float lnt0 = sc[256 + m0 + g],  lnt1 = sc[256 + m0 + g + 8];
    float hnt0 = sc[m0 + g],        hnt1 = sc[m0 + g + 8];

    // ============ Phase A: theta + l Grams -> tp[8][4] ============
    unsigned aT[4][4], aL[2][4];
    #pragma unroll
    for (int ks = 0; ks < 4; ks++) {
        const float* p0 = S + S_PT + (m0 + g) * 36 + ks * 8 + q;
        const float* p1 = S + S_PT + (m0 + g + 8) * 36 + ks * 8 + q;
        aT[ks][0] = ldsu(p0);     aT[ks][1] = ldsu(p1);
        aT[ks][2] = ldsu(p0 + 4); aT[ks][3] = ldsu(p1 + 4);
    }
    #pragma unroll
    for (int ks = 0; ks < 2; ks++) {
        const float* p0 = S + S_LT + (m0 + g) * 20 + ks * 8 + q;
        const float* p1 = S + S_LT + (m0 + g + 8) * 20 + ks * 8 + q;
        aL[ks][0] = ldsu(p0);     aL[ks][1] = ldsu(p1);
        aL[ks][2] = ldsu(p0 + 4); aL[ks][3] = ldsu(p1 + 4);
    }

    float tp[8][4];
    const float2* slut = (const float2*)(S + S_LUT);

    #pragma unroll
    for (int n = 0; n < 8; n++) {
        int n0 = (nh * 8 + n) * 8;
        float dT[4] = {0.f, 0.f, 0.f, 0.f};
        #pragma unroll
        for (int ks = 0; ks < 4; ks++) {
            const float* bp = S + S_QS + (n0 + g) * 36 + ks * 8 + q;
            unsigned b[2] = { ldsu(bp), ldsu(bp + 4) };
            mma8(dT, aT[ks], b);
        }
        float dL[4] = {0.f, 0.f, 0.f, 0.f};
        #pragma unroll
        for (int ks = 0; ks < 2; ks++) {
            const float* bp = S + S_LS + (n0 + g) * 20 + ks * 8 + q;
            unsigned b[2] = { ldsu(bp), ldsu(bp + 4) };
            mma8(dL, aL[ks], b);
        }
        int c0 = n0 + 2 * q, c1 = c0 + 1;
        float cs0  = sc[640 + c0], cs1  = sc[640 + c1];
        float lns0 = sc[384 + c0], lns1 = sc[384 + c1];
        float ctv[4]  = { ct0, ct0, ct1, ct1 };
        float csv[4]  = { cs0, cs1, cs0, cs1 };
        float lntv[4] = { lnt0, lnt0, lnt1, lnt1 };
        float lnsv[4] = { lns0, lns1, lns0, lns1 };
        #pragma unroll
        for (int e = 0; e < 4; e++) {
            float a = w2b + ctv[e] + csv[e] + dT[e];
            float u = a * a;
            float Th = a * fmaf(u, fmaf(u, fmaf(u, -0.05396825397f,
                                 0.13333333333f), -0.33333333333f), 1.0f);
            float dl2 = fmaxf(fmaf(-2.f, dL[e], lntv[e] + lnsv[e]), 0.f);
            float t   = fminf(dl2 * LUTSCL, (float)(LUTN - 1));
            int   ix  = (int)t;
            float fr  = t - (float)ix;
            float2 lv = slut[ix];
            tp[n][e] = -Th * fmaf(fr, lv.y, lv.x);
        }
    }

    // ============ Phase B: h Gram (bf16, K=128 -> 8 ksteps) ============
    asm volatile("cp.async.wait_group 0;" ::: "memory");
    __syncthreads();

    const unsigned* HBT = (const unsigned*)(S + S_HBT);
    const unsigned* HBS = (const unsigned*)(S + S_HBS);

    float acc[8][4];
    #pragma unroll
    for (int n = 0; n < 8; n++)
        #pragma unroll
        for (int e = 0; e < 4; e++) acc[n][e] = 0.f;

    #pragma unroll 4
    for (int ks = 0; ks < 8; ks++) {
        int kb = ks * 8;
        const unsigned* pT = HBT + (m0 + g) * 68 + kb + q;
        unsigned a[4] = { pT[0], pT[8 * 68], pT[4], pT[8 * 68 + 4] };
        #pragma unroll
        for (int n = 0; n < 8; n++) {
            const unsigned* pS = HBS + ((nh * 8 + n) * 8 + g) * 68 + kb + q;
            unsigned b[2] = { pS[0], pS[4] };
            mma16(acc[n], a, b);
        }
    }

    // ============ epilogue ============
    {
        size_t orow0 = ((size_t)(bz * TT + t0 + m0 + g)) * TT + s0;
        size_t orow1 = orow0 + (size_t)8 * TT;
        #pragma unroll
        for (int n = 0; n < 8; n++) {
            int c0 = (nh * 8 + n) * 8 + 2 * q;
            float hns0 = sc[128 + c0], hns1 = sc[128 + c0 + 1];
            float d0 = fmaxf(fmaf(-2.f, acc[n][0], hnt0 + hns0), 0.f) + EPS2;
            float d1 = fmaxf(fmaf(-2.f, acc[n][1], hnt0 + hns1), 0.f) + EPS2;
            float d2 = fmaxf(fmaf(-2.f, acc[n][2], hnt1 + hns0), 0.f) + EPS2;
            float d3 = fmaxf(fmaf(-2.f, acc[n][3], hnt1 + hns1), 0.f) + EPS2;
            float2 v0 = make_float2(tp[n][0] * rsqrtf(d0), tp[n][1] * rsqrtf(d1));
            float2 v1 = make_float2(tp[n][2] * rsqrtf(d2), tp[n][3] * rsqrtf(d3));
            *(float2*)(out + orow0 + c0) = v0;
            *(float2*)(out + orow1 + c0) = v1;
        }
    }
}

// ---------------------------------------------------------------------------
extern "C" void kernel_launch(void* const* d_in, const int* in_sizes, int n_in,
                              void* d_out, int out_size)
{
    (void)in_sizes; (void)n_in; (void)out_size;
    const float* h       = (const float*)d_in[0];
    const float* hsrc    = (const float*)d_in[1];
    const float* W_l     = (const float*)d_in[2];
    const float* W_theta = (const float*)d_in[3];
    const float* phi1_w  = (const float*)d_in[4];
    const float* phi1_b  = (const float*)d_in[5];
    const float* phi2_w  = (const float*)d_in[6];
    const float* phi2_b  = (const float*)d_in[7];
    const float* wq      = (const float*)d_in[8];
    const float* ws      = (const float*)d_in[9];
    const float* wd      = (const float*)d_in[10];
    const float* b1      = (const float*)d_in[11];
    const float* w2_w    = (const float*)d_in[12];
    const float* w2_b    = (const float*)d_in[13];
    float* out = (float*)d_out;

    cudaFuncSetAttribute(prep_kernel,
                         cudaFuncAttributeMaxDynamicSharedMemorySize, PREP_SMEM);
    cudaFuncSetAttribute(main_kernel,
                         cudaFuncAttributeMaxDynamicSharedMemorySize, MAIN_SMEM);

    prep_kernel<<<dim3(64, 3), 128, PREP_SMEM>>>(h, hsrc, W_l, W_theta,
                                                 wq, ws, wd, b1, w2_w,
                                                 phi1_w, phi1_b, phi2_w, phi2_b);
    main_kernel<<<dim3(4, 4, BB), 512, MAIN_SMEM>>>(w2_b, out);
}